// round 17
// baseline (speedup 1.0000x reference)
#include <cuda_runtime.h>
#include <cuda_fp16.h>
#include <stdint.h>
#include <math.h>

#define Bt 32
#define Ct 684
#define Ht 16
#define Wt 64
#define HWt 1024
#define HIDt 256
#define At 512
#define NPATCH 121
#define KCOMB 805
#define NST 13
#define NPOS 32768
#define NCTA 148
#define NPJ 160                 // padded patch rows (121 real + zeros)
#define ALPHA_OFF (Bt*Ct)
#define ASUM_OFF  (Bt*Ct + Bt*HWt)

// dynamic smem: Wbuf[2]@0 (65536) | stg[3]@65536 (3*17408 = 52224)
#define WB  0
#define STG 65536
#define STGB 17408              // 64 rows * 272 B
#define SMEM_SZ 117760
#define WT 32768
#define NTILE 512

// ---------------- device scratch ----------------
__device__ __align__(1024) unsigned char g_W[(size_t)2 * NST * WT];
__device__ __align__(16) __half g_cnn16[(size_t)Bt * Ct * HWt];   // 44.8 MB
__device__ __align__(16) __half g_P[(size_t)Bt * NPJ * HWt];      // 10.5 MB (zero-padded)
__device__ float g_Weff[At * NPATCH];
__device__ float g_query[Bt * At];
__device__ float g_Epart[2 * NPOS];
__device__ int g_cnt[4];

// ---------------- helpers ----------------
__device__ __forceinline__ uint32_t smem_u32(const void* p) {
    uint32_t a;
    asm("{ .reg .u64 t; cvta.to.shared.u64 t, %1; cvt.u32.u64 %0, t; }" : "=r"(a) : "l"(p));
    return a;
}
__device__ __forceinline__ void mb_init(uint32_t a, uint32_t c) {
    asm volatile("mbarrier.init.shared.b64 [%0], %1;" :: "r"(a), "r"(c) : "memory");
}
__device__ __forceinline__ void mb_tx(uint32_t a, uint32_t bytes) {
    asm volatile("mbarrier.arrive.expect_tx.shared.b64 _, [%0], %1;" :: "r"(a), "r"(bytes) : "memory");
}
__device__ __forceinline__ void mb_wait(uint32_t a, uint32_t par) {
    uint32_t d = 0;
    while (!d)
        asm volatile("{ .reg .pred p; mbarrier.try_wait.parity.acquire.cta.shared::cta.b64 p,[%1],%2,0x989680; selp.b32 %0,1,0,p; }"
                     : "=r"(d) : "r"(a), "r"(par) : "memory");
}
__device__ __forceinline__ void blkcp(uint32_t dst, const void* src, uint32_t bytes, uint32_t mbar) {
    asm volatile("cp.async.bulk.shared::cta.global.mbarrier::complete_tx::bytes [%0], [%1], %2, [%3];"
                 :: "r"(dst), "l"(src), "r"(bytes), "r"(mbar) : "memory");
}
__device__ __forceinline__ void cpa16(uint32_t dst, const void* src) {
    asm volatile("cp.async.cg.shared.global [%0], [%1], 16;" :: "r"(dst), "l"(src));
}
#define BARS(id, n) asm volatile("bar.sync %0, %1;" :: "r"(id), "r"(n) : "memory")
#define LDMX4(r0,r1,r2,r3,addr) \
    asm volatile("ldmatrix.sync.aligned.m8n8.x4.shared.b16 {%0,%1,%2,%3}, [%4];" \
                 : "=r"(r0),"=r"(r1),"=r"(r2),"=r"(r3) : "r"(addr))
#define LDMX4T(r0,r1,r2,r3,addr) \
    asm volatile("ldmatrix.sync.aligned.m8n8.x4.trans.shared.b16 {%0,%1,%2,%3}, [%4];" \
                 : "=r"(r0),"=r"(r1),"=r"(r2),"=r"(r3) : "r"(addr))
#define MMA(d,a,b) \
    asm volatile("mma.sync.aligned.m16n8k16.row.col.f32.f16.f16.f32 " \
                 "{%0,%1,%2,%3},{%4,%5,%6,%7},{%8,%9},{%0,%1,%2,%3};" \
                 : "+f"(d[0]),"+f"(d[1]),"+f"(d[2]),"+f"(d[3]) \
                 : "r"(a[0]),"r"(a[1]),"r"(a[2]),"r"(a[3]),"r"(b[0]),"r"(b[1]))

__device__ __forceinline__ uint32_t h2u(float v0, float v1) {
    __half2 h = __floats2half2_rn(v0, v1);
    return *(uint32_t*)&h;
}
__device__ __forceinline__ float ftanh(float x) {
    float e = __expf(2.0f * x);
    return 1.0f - __fdividef(2.0f, e + 1.0f);
}
__device__ __forceinline__ void gridbar(int ph) {
    __syncthreads();
    if (threadIdx.x == 0) {
        __threadfence();
        atomicAdd(&g_cnt[ph], 1);
        while (atomicAdd(&g_cnt[ph], 0) < NCTA) { }
        __threadfence();
    }
    __syncthreads();
}

__global__ void k_zero() {
    if (threadIdx.x < 4) g_cnt[threadIdx.x] = 0;
}

// ---------------- main: fully-fused persistent megakernel ----------------
__global__ __launch_bounds__(256, 1)
void k_mma(const float* __restrict__ cnn, const float* __restrict__ hidden,
           const float* __restrict__ asum, const float* __restrict__ mask,
           const float* __restrict__ Wh, const float* __restrict__ bh,
           const float* __restrict__ Wec, const float* __restrict__ bec,
           const float* __restrict__ Wac, const float* __restrict__ Waw,
           const float* __restrict__ Wv, const float* __restrict__ bv,
           float* __restrict__ out) {
    extern __shared__ char dsm[];
    __shared__ float qs[256], ws[256], esm[512];
    __shared__ __align__(8) uint64_t mbars[2];
    const uint32_t sb = smem_u32(dsm);
    const uint32_t mbF = smem_u32(&mbars[0]);
    const int tid = threadIdx.x, lane = tid & 31, w = tid >> 5;
    const int wm = w >> 2, wn = w & 3;
    const int gtid = blockIdx.x * 256 + tid;
    const int gstride = NCTA * 256;

    // ================= PHASE A: query, Weff, cnn16, patches (full chip) =================
    // query[b][a] = hidden[b] . Wh[a] + bh[a] + bec[a]
    for (int idx = gtid; idx < Bt * At; idx += gstride) {
        int a = idx & (At - 1), b = idx >> 9;
        const float* hr = hidden + b * HIDt;
        const float* wr = Wh + a * HIDt;
        float s = 0.f;
        #pragma unroll 8
        for (int k = 0; k < HIDt; ++k) s = fmaf(wr[k], hr[k], s);
        g_query[idx >> 9 == b ? b * At + a : 0] = s + bh[a] + bec[a];
    }
    // Weff[a][j] = sum_c Waw[a][c] * Wac[c][j]
    for (int idx = gtid; idx < At * NPATCH; idx += gstride) {
        int a = idx / NPATCH, j = idx - a * NPATCH;
        float s = 0.f;
        #pragma unroll 4
        for (int c = 0; c < At; ++c) s = fmaf(Waw[a * At + c], Wac[c * NPATCH + j], s);
        g_Weff[idx] = s;
    }
    // cnn16: streaming fp32 -> fp16 (float4 granules)
    {
        const int n4 = (Bt * Ct * HWt) / 4;   // 5,603,328
        for (int idx = gtid; idx < n4; idx += gstride) {
            float4 v = *(const float4*)(cnn + (size_t)idx * 4);
            uint2 u;
            u.x = h2u(v.x, v.y);
            u.y = h2u(v.z, v.w);
            *(uint2*)(g_cnn16 + (size_t)idx * 4) = u;
        }
    }
    // patches: fp16 im2col rows (pairs of consecutive pos)
    {
        const int n2 = (Bt * NPJ * HWt) / 2;  // 2,621,440
        for (int idx = gtid; idx < n2; idx += gstride) {
            int e0 = idx * 2;
            int b = e0 / (NPJ * HWt), r2 = e0 - b * (NPJ * HWt);
            int j = r2 >> 10, pos = r2 & 1023;
            float v0 = 0.f, v1 = 0.f;
            if (j < NPATCH) {
                int dh = j / 11 - 5, dw = j % 11 - 5;
                int hh = (pos >> 6) + dh;
                int w0 = (pos & 63) + dw, w1 = ((pos + 1) & 63) + dw;
                if (hh >= 0 && hh < Ht) {
                    if (w0 >= 0 && w0 < Wt) v0 = asum[b * HWt + hh * Wt + w0];
                    if (w1 >= 0 && w1 < Wt) v1 = asum[b * HWt + hh * Wt + w1];
                }
            }
            *(uint32_t*)(g_P + e0) = h2u(v0, v1);
        }
    }
    gridbar(0);

    // ================= PHASE B: W tile pack (needs Weff) =================
    {
        float* tb = (float*)(dsm + STG);    // [64][129] transpose buffer (33 KB < 52 KB)
        for (int unit = blockIdx.x; unit < 52; unit += NCTA) {
            int s = unit % NST, ag = unit / NST;
            #pragma unroll 4
            for (int i = 0; i < 32; ++i) {
                int kk = lane + (i & 1) * 32;
                int a = w + (i >> 1) * 8;
                int k = s * 64 + kk, aa = ag * 128 + a;
                float v = 0.f;
                if (k < Ct) v = Wec[aa * Ct + k];
                else if (k < KCOMB) v = g_Weff[aa * NPATCH + (k - Ct)];
                tb[kk * 129 + a] = v;
            }
            __syncthreads();
            unsigned char* tile = g_W + ((size_t)((ag >> 1) * NST + s) << 15);
            const int rbase = (ag & 1) * 128;
            #pragma unroll
            for (int i = 0; i < 4; ++i) {
                int idx = i * 256 + tid;
                int r = idx >> 3, ch = idx & 7;
                uint32_t hv[4];
                #pragma unroll
                for (int j = 0; j < 4; ++j)
                    hv[j] = h2u(tb[(ch * 8 + 2 * j) * 129 + r], tb[(ch * 8 + 2 * j + 1) * 129 + r]);
                int r2 = rbase + r;
                uint32_t off = r2 * 128 + ((ch ^ (r2 & 7)) << 4);
                *(uint4*)(tile + off) = make_uint4(hv[0], hv[1], hv[2], hv[3]);
            }
            __syncthreads();
        }
    }
    gridbar(1);

    // ================= GEMM mainloop (R16, byte-identical) =================
    if (tid == 0) { mb_init(mbF, 1); mb_init(mbF + 8, 1); }
    __syncthreads();

    int tiles[4], ntiles = 0;
    for (int t = blockIdx.x; t < NTILE; t += NCTA) tiles[ntiles++] = t;
    const int total = ntiles * NST;

    auto cpaX = [&](int g) {
        int ti2 = g / NST, s2 = g - ti2 * NST, bx = tiles[ti2] >> 1;
        int b2 = bx >> 3, pos0b = (bx & 7) * 128;
        int k0 = s2 * 64;
        uint32_t dstb = sb + STG + (g % 3) * STGB;
        const __half* c16 = g_cnn16 + (size_t)b2 * Ct * HWt + pos0b;
        const __half* pp  = g_P + (size_t)b2 * NPJ * HWt + pos0b;
        #pragma unroll
        for (int i = 0; i < 4; ++i) {
            int id = i * 256 + tid;
            int row = id >> 4, c = id & 15;
            int k = k0 + row;
            const __half* src = (k < Ct) ? (c16 + (size_t)k * HWt) : (pp + (size_t)(k - Ct) * HWt);
            cpa16(dstb + row * 272 + c * 16, (const char*)src + c * 16);
        }
    };

    {
        int by0 = tiles[0] & 1;
        if (tid == 0) {
            mb_tx(mbF, WT);
            blkcp(sb + WB, g_W + ((size_t)(by0 * NST) << 15), WT, mbF);
        }
        cpaX(0);
        asm volatile("cp.async.commit_group;" ::: "memory");
        if (total > 1) cpaX(1);
        asm volatile("cp.async.commit_group;" ::: "memory");
    }

    float acc[4][8][4];
    #pragma unroll
    for (int mt = 0; mt < 4; ++mt)
        #pragma unroll
        for (int nt = 0; nt < 8; ++nt)
            #pragma unroll
            for (int r = 0; r < 4; ++r) acc[mt][nt][r] = 0.f;

    int ti = 0, s = 0;
    for (int g = 0; g < total; ++g) {
        asm volatile("cp.async.wait_group 1;" ::: "memory");
        __syncthreads();
        if (g + 2 < total) cpaX(g + 2);
        asm volatile("cp.async.commit_group;" ::: "memory");
        if (tid == 0 && g + 1 < total) {
            int nti = (g + 1) / NST, ns2 = (g + 1) - nti * NST, nby = tiles[nti] & 1;
            uint32_t fb = mbF + ((g + 1) & 1) * 8;
            mb_tx(fb, WT);
            blkcp(sb + WB + ((g + 1) & 1) * WT, g_W + ((size_t)(nby * NST + ns2) << 15), WT, fb);
        }
        mb_wait(mbF + (g & 1) * 8, (g >> 1) & 1);
        {
            const uint32_t xg = sb + STG + (g % 3) * STGB;
            const uint32_t wb = sb + WB + (g & 1) * WT;
            #pragma unroll
            for (int ks = 0; ks < 4; ++ks) {
                uint32_t bf[8][2];
                const int browb = wn * 64 + (lane & 7) + ((lane >> 4) & 1) * 8;
                const int bc = 2 * ks + ((lane >> 3) & 1);
                #pragma unroll
                for (int np = 0; np < 4; ++np) {
                    int r = browb + np * 16;
                    uint32_t boff = r * 128 + ((bc ^ (r & 7)) << 4);
                    LDMX4(bf[np*2][0], bf[np*2][1], bf[np*2+1][0], bf[np*2+1][1], wb + boff);
                }
                const int kr = ks * 16 + (lane & 7) + ((lane >> 4) & 1) * 8;
                const int mcb = wm * 64 + ((lane >> 3) & 1) * 8;
                #pragma unroll
                for (int mt = 0; mt < 4; ++mt) {
                    uint32_t af[4];
                    uint32_t aaddr = xg + kr * 272 + (mcb + mt * 16) * 2;
                    LDMX4T(af[0], af[1], af[2], af[3], aaddr);
                    #pragma unroll
                    for (int nt = 0; nt < 8; ++nt)
                        MMA(acc[mt][nt], af, bf[nt]);
                }
            }
        }

        if (++s == NST) {
            const int bx = tiles[ti] >> 1, by = tiles[ti] & 1;
            const int pos0 = bx * 128, a0 = by * 256, b = bx >> 3;
            __syncthreads();
            qs[tid] = g_query[b * At + a0 + tid];
            ws[tid] = Wv[a0 + tid];
            __syncthreads();
            #pragma unroll
            for (int mt = 0; mt < 4; ++mt) {
                float er0 = 0.f, er1 = 0.f;
                #pragma unroll
                for (int nt = 0; nt < 8; ++nt) {
                    int col = wn * 64 + nt * 8 + (lane & 3) * 2;
                    float q0 = qs[col], q1 = qs[col + 1];
                    float w0 = ws[col], w1 = ws[col + 1];
                    er0 = fmaf(w0, ftanh(acc[mt][nt][0] + q0), er0);
                    er0 = fmaf(w1, ftanh(acc[mt][nt][1] + q1), er0);
                    er1 = fmaf(w0, ftanh(acc[mt][nt][2] + q0), er1);
                    er1 = fmaf(w1, ftanh(acc[mt][nt][3] + q1), er1);
                }
                er0 += __shfl_xor_sync(0xffffffffu, er0, 1);
                er0 += __shfl_xor_sync(0xffffffffu, er0, 2);
                er1 += __shfl_xor_sync(0xffffffffu, er1, 1);
                er1 += __shfl_xor_sync(0xffffffffu, er1, 2);
                if ((lane & 3) == 0) {
                    int r = wm * 64 + mt * 16 + (lane >> 2);
                    esm[r * 4 + wn] = er0;
                    esm[(r + 8) * 4 + wn] = er1;
                }
            }
            __syncthreads();
            if (tid < 128)
                g_Epart[by * NPOS + pos0 + tid] =
                    esm[tid * 4] + esm[tid * 4 + 1] + esm[tid * 4 + 2] + esm[tid * 4 + 3];
            #pragma unroll
            for (int mt = 0; mt < 4; ++mt)
                #pragma unroll
                for (int nt = 0; nt < 8; ++nt)
                    #pragma unroll
                    for (int r = 0; r < 4; ++r) acc[mt][nt][r] = 0.f;
            s = 0; ++ti;
        }
    }

    // ==== all Epart written ====
    gridbar(2);

    // softmax per batch (CTAs 0-31)
    if (blockIdx.x < Bt) {
        const int b = blockIdx.x;
        float* exs = (float*)dsm;
        float bvv = bv[0];
        float ev[4], m = -1e30f;
        #pragma unroll
        for (int i = 0; i < 4; ++i) {
            int p = tid + i * 256;
            float e = bvv + g_Epart[b * HWt + p] + g_Epart[NPOS + b * HWt + p];
            ev[i] = e; m = fmaxf(m, e);
        }
        esm[tid] = m; __syncthreads();
        for (int s2 = 128; s2 > 0; s2 >>= 1) { if (tid < s2) esm[tid] = fmaxf(esm[tid], esm[tid + s2]); __syncthreads(); }
        m = esm[0];
        __syncthreads();
        float ls = 0.f;
        #pragma unroll
        for (int i = 0; i < 4; ++i) {
            int p = tid + i * 256;
            float v = expf(ev[i] - m) * mask[b * HWt + p];
            exs[p] = v; ls += v;
        }
        esm[tid] = ls; __syncthreads();
        for (int s2 = 128; s2 > 0; s2 >>= 1) { if (tid < s2) esm[tid] += esm[tid + s2]; __syncthreads(); }
        float inv = 1.f / (esm[0] + 1e-10f);
        #pragma unroll
        for (int i = 0; i < 4; ++i) {
            int p = tid + i * 256;
            float al = exs[p] * inv;
            out[ALPHA_OFF + b * HWt + p] = al;
            out[ASUM_OFF + b * HWt + p] = al + asum[b * HWt + p];
        }
    }

    gridbar(3);

    // context: full chip, 2 c-rows per block-iteration
    {
        const int cr = tid >> 7, l = tid & 127;
        const int wq = (tid >> 5) & 3;
        for (int idx = blockIdx.x; idx < (Ct / 2) * Bt; idx += NCTA) {
            int b = idx / (Ct / 2);
            int cp = idx - b * (Ct / 2);
            int c = cp * 2 + cr;
            const float4* f = (const float4*)(cnn + (size_t)(b * Ct + c) * HWt);
            const float4* al = (const float4*)(out + ALPHA_OFF + b * HWt);
            float sdot = 0.f;
            #pragma unroll
            for (int i = 0; i < 2; ++i) {
                float4 a4 = al[l + i * 128], f4 = f[l + i * 128];
                sdot += a4.x * f4.x + a4.y * f4.y + a4.z * f4.z + a4.w * f4.w;
            }
            #pragma unroll
            for (int o = 16; o > 0; o >>= 1) sdot += __shfl_xor_sync(0xffffffffu, sdot, o);
            if (lane == 0) esm[cr * 4 + wq] = sdot;
            BARS(3 + cr, 128);
            if (l == 0)
                out[b * Ct + c] = esm[cr * 4] + esm[cr * 4 + 1] + esm[cr * 4 + 2] + esm[cr * 4 + 3];
            BARS(3 + cr, 128);
        }
    }
}

// ---------------- launch ----------------
extern "C" void kernel_launch(void* const* d_in, const int* in_sizes, int n_in,
                              void* d_out, int out_size) {
    const float* cnn    = (const float*)d_in[0];
    const float* hidden = (const float*)d_in[1];
    const float* asum   = (const float*)d_in[2];
    const float* mask   = (const float*)d_in[3];
    const float* Wh     = (const float*)d_in[4];
    const float* bh     = (const float*)d_in[5];
    const float* Wec    = (const float*)d_in[6];
    const float* bec    = (const float*)d_in[7];
    const float* Wac    = (const float*)d_in[8];
    const float* Waw    = (const float*)d_in[9];
    const float* Wv     = (const float*)d_in[10];
    const float* bv     = (const float*)d_in[11];
    float* out = (float*)d_out;

    cudaFuncSetAttribute(k_mma, cudaFuncAttributeMaxDynamicSharedMemorySize, SMEM_SZ);

    k_zero<<<1, 32>>>();
    k_mma<<<NCTA, 256, SMEM_SZ>>>(cnn, hidden, asum, mask, Wh, bh, Wec, bec,
                                  Wac, Waw, Wv, bv, out);
}